// round 9
// baseline (speedup 1.0000x reference)
#include <cuda_runtime.h>
#include <cuda_bf16.h>
#include <cstdint>

#define Bb 64
#define Vv 64
#define Tt 256
#define Ff 64
#define NEG_SLOPE 0.01f

// Precomputed adjacency (NON-transposed): adj[t][v][w] = sigmoid(A[t][v][w]) off-diag, 1 on diag.
__device__ float g_adj[(size_t)Tt * Vv * Vv];   // 4 MB

__device__ __forceinline__ float fast_sigmoid(float x) {
    // sigmoid(x) = 0.5 + 0.5*tanh(0.5*x): single MUFU.TANH instead of EX2+RCP.
    float th;
    asm("tanh.approx.f32 %0, %1;" : "=f"(th) : "f"(0.5f * x));
    return fmaf(0.5f, th, 0.5f);
}

// ---------------------------------------------------------------------------
// Prep: now purely elementwise (no transpose, no smem): adj[t][v][w] in the
// SAME layout as A. float4 in/out, 512 blocks. ~1.2us.
// ---------------------------------------------------------------------------
__global__ __launch_bounds__(256) void adj_prep(const float* __restrict__ A) {
    const int base4 = (blockIdx.x * 256 + threadIdx.x) * 2;   // float4 index, 2 per thread
    const float4* A4 = reinterpret_cast<const float4*>(A);
    float4* D4 = reinterpret_cast<float4*>(g_adj);

#pragma unroll
    for (int k = 0; k < 2; k++) {
        int idx4 = base4 + k;                 // global float4 idx: t*1024 + v*16 + wq
        int v = (idx4 >> 4) & 63;
        int wq = idx4 & 15;
        float4 a = A4[idx4];
        float4 r;
        r.x = (v == 4 * wq + 0) ? 1.0f : fast_sigmoid(a.x);
        r.y = (v == 4 * wq + 1) ? 1.0f : fast_sigmoid(a.y);
        r.z = (v == 4 * wq + 2) ? 1.0f : fast_sigmoid(a.z);
        r.w = (v == 4 * wq + 3) ? 1.0f : fast_sigmoid(a.w);
        D4[idx4] = r;
    }
}

// ---------------------------------------------------------------------------
// Fused GEMM + expand. R4 grid/store shape (2048 blocks, 256 thr), but the
// 16 KB sAT smem staging is GONE: thread (g, v) dots the contiguous 256B row
// adj[t][v][:] (16x LDG.128, unroll-4 to bound regs) against sX rows. Groups
// 2-4 hit L1 on the same rows. Smem 4 KB; prologue shrinks to the X gather.
// ---------------------------------------------------------------------------
__global__ __launch_bounds__(256) void fused_kernel(const float* __restrict__ X,
                                                    const float* __restrict__ W,
                                                    float* __restrict__ out) {
    const int t  = blockIdx.x;
    const int b0 = blockIdx.y << 3;    // 0,8,...,56

    __shared__ float sX[8][Vv];        // 2 KB
    __shared__ float sH[8][Vv];        // 2 KB

    const int tid = threadIdx.x;

    // Per-thread W quad, leaky pre-selected: leaky(h*w) = h * (h>=0 ? wp : wn)
    float4 w4 = reinterpret_cast<const float4*>(W)[tid & 15];
    float4 wp, wn;
    wp.x = (w4.x >= 0.f) ? w4.x : NEG_SLOPE * w4.x;
    wp.y = (w4.y >= 0.f) ? w4.y : NEG_SLOPE * w4.y;
    wp.z = (w4.z >= 0.f) ? w4.z : NEG_SLOPE * w4.z;
    wp.w = (w4.w >= 0.f) ? w4.w : NEG_SLOPE * w4.w;
    wn.x = (w4.x >= 0.f) ? NEG_SLOPE * w4.x : w4.x;
    wn.y = (w4.y >= 0.f) ? NEG_SLOPE * w4.y : w4.y;
    wn.z = (w4.z >= 0.f) ? NEG_SLOPE * w4.z : w4.z;
    wn.w = (w4.w >= 0.f) ? NEG_SLOPE * w4.w : w4.w;

    // Gather X[b0..b0+7][*][t]
#pragma unroll
    for (int k = 0; k < 2; k++) {
        int idx = tid + k * 256;           // bb*64 + w
        int bb = idx >> 6, w = idx & 63;
        sX[bb][w] = __ldg(&X[((size_t)(b0 + bb) * Vv + w) * Tt + t]);
    }
    __syncthreads();

    // Mini-GEMM: thread (v = tid&63, g = tid>>6) computes h[g][v], h[g+4][v]
    // by dotting the contiguous adj row v against sX rows g, g+4.
    {
        const int v = tid & 63;
        const int g = tid >> 6;
        const float4* arow = reinterpret_cast<const float4*>(g_adj + (size_t)t * 4096 + v * 64);
        const float4* x0q = reinterpret_cast<const float4*>(&sX[g][0]);
        const float4* x1q = reinterpret_cast<const float4*>(&sX[g + 4][0]);
        float a0 = 0.f, a1 = 0.f;
#pragma unroll 4
        for (int wq = 0; wq < 16; wq++) {
            float4 s  = __ldg(arow + wq);
            float4 x0 = x0q[wq];
            float4 x1 = x1q[wq];
            a0 = fmaf(s.x, x0.x, fmaf(s.y, x0.y, fmaf(s.z, x0.z, fmaf(s.w, x0.w, a0))));
            a1 = fmaf(s.x, x1.x, fmaf(s.y, x1.y, fmaf(s.z, x1.z, fmaf(s.w, x1.w, a1))));
        }
        sH[g][v] = a0;
        sH[g + 4][v] = a1;
    }
    __syncthreads();

    // Store phase: 8 x 16 KB tiles of leaky(h*W), coalesced float4 streaming stores.
    float4* obase = reinterpret_cast<float4*>(out);
#pragma unroll
    for (int bb = 0; bb < 8; bb++) {
        float4* o = obase + ((size_t)(b0 + bb) * Tt + t) * 1024;
        const float* hrow = sH[bb];
#pragma unroll
        for (int k = 0; k < 4; k++) {
            int q = tid + k * 256;            // q&15 == tid&15, q>>4 = v
            float h = hrow[q >> 4];
            bool pos = (h >= 0.f);
            float4 r;
            r.x = h * (pos ? wp.x : wn.x);
            r.y = h * (pos ? wp.y : wn.y);
            r.z = h * (pos ? wp.z : wn.z);
            r.w = h * (pos ? wp.w : wn.w);
            __stcs(o + q, r);
        }
    }
}

extern "C" void kernel_launch(void* const* d_in, const int* in_sizes, int n_in,
                              void* d_out, int out_size) {
    const float* X = (const float*)d_in[0];   // [B, V, T]
    const float* A = (const float*)d_in[1];   // [T, V, V]
    const float* W = (const float*)d_in[2];   // [F, 1]
    float* out = (float*)d_out;               // [B, T, V*F]

    adj_prep<<<512, 256>>>(A);
    dim3 grid(Tt, Bb / 8);
    fused_kernel<<<grid, 256>>>(X, W, out);
}

// round 10
// speedup vs baseline: 1.4217x; 1.4217x over previous
#include <cuda_runtime.h>
#include <cuda_bf16.h>
#include <cstdint>

#define Bb 64
#define Vv 64
#define Tt 256
#define Ff 64
#define NEG_SLOPE 0.01f

// Precomputed transposed adjacency: adjT[t][w][v] = sigmoid(A[t][v][w]) off-diag, 1 on diag.
__device__ float g_adjT[(size_t)Tt * Vv * Vv];   // 4 MB
// Transposed X: XT[t][b][w] = X[b][w][t] (makes fused-kernel X loads coalesced)
__device__ float g_XT[(size_t)Tt * Bb * Vv];     // 4 MB

__device__ __forceinline__ float fast_sigmoid(float x) {
    // sigmoid(x) = 0.5 + 0.5*tanh(0.5*x): single MUFU.TANH instead of EX2+RCP.
    float th;
    asm("tanh.approx.f32 %0, %1;" : "=f"(th) : "f"(0.5f * x));
    return fmaf(0.5f, th, 0.5f);
}

// ---------------------------------------------------------------------------
// Combined prep, ONE launch so the two independent transposes run
// concurrently across SMs instead of serializing on the stream:
//   blocks [0,512):    adjT[t][w][v] = sigmoid(A[t][v][w]) (+unit diag), via
//                      32x64 smem tile; tanh-based (R8), both sides coalesced.
//   blocks [512,1536): XT[t][b][w] = X[b][w][t], 32x32 smem tile (R7).
// ---------------------------------------------------------------------------
__global__ __launch_bounds__(256) void prep_combined(const float* __restrict__ A,
                                                     const float* __restrict__ X) {
    __shared__ float sm[32][Vv + 1];   // max of both uses (8.1 KB)

    const int tid = threadIdx.x;
    const int bid = blockIdx.x;

    if (bid < 512) {
        // ---- adj prep: t = bid>>1, v-half = bid&1 ----
        const int t  = bid >> 1;
        const int v0 = (bid & 1) * 32;

        const float4* A4 = reinterpret_cast<const float4*>(A) + (size_t)t * 1024 + v0 * 16;
#pragma unroll
        for (int k = 0; k < 2; k++) {
            int idx4 = tid + k * 256;          // vloc*16 + wq
            int vloc = idx4 >> 4, wq = idx4 & 15;
            int v = v0 + vloc;
            float4 a = A4[idx4];
            float av[4] = {a.x, a.y, a.z, a.w};
#pragma unroll
            for (int i = 0; i < 4; i++) {
                int w = wq * 4 + i;
                sm[vloc][w] = (v == w) ? 1.0f : fast_sigmoid(av[i]);
            }
        }
        __syncthreads();

        float* dst = g_adjT + (size_t)t * 4096 + v0;
#pragma unroll
        for (int k = 0; k < 8; k++) {
            int idx = tid + k * 256;           // w*32 + vloc
            int w = idx >> 5, vloc = idx & 31;
            dst[w * 64 + vloc] = sm[vloc][w];
        }
    } else {
        // ---- X transpose: bid2 in [0,1024): t-tile, b, w-half ----
        const int bid2 = bid - 512;
        const int t0 = (bid2 & 7) * 32;        // 0..224
        const int b  = (bid2 >> 3) & 63;       // 0..63
        const int w0 = (bid2 >> 9) * 32;       // 0 or 32

        const int j  = tid & 31;
        const int i0 = tid >> 5;               // 0..7

#pragma unroll
        for (int k = 0; k < 4; k++) {
            int i = i0 + k * 8;                // w offset on read
            sm[i][j] = X[((size_t)b * Vv + (w0 + i)) * Tt + (t0 + j)];
        }
        __syncthreads();
#pragma unroll
        for (int k = 0; k < 4; k++) {
            int i = i0 + k * 8;                // t offset on write
            g_XT[(size_t)(t0 + i) * (Bb * Vv) + (size_t)b * Vv + (w0 + j)] = sm[j][i];
        }
    }
}

// ---------------------------------------------------------------------------
// Fused GEMM + expand — R7's fused verbatim (measured ~41.9us there):
// 2048 blocks, 256 thr, 20 KB smem, 8/SM. sAT staged in smem [w][v]
// (warp-contiguous reads), X via ONE coalesced 2 KB XT load (the in-kernel
// stride-1KB gather costs ~6us of L1tex contention — R8 vs R7 delta).
// ---------------------------------------------------------------------------
__global__ __launch_bounds__(256) void fused_kernel(const float* __restrict__ W,
                                                    float* __restrict__ out) {
    const int t  = blockIdx.x;
    const int b0 = blockIdx.y << 3;    // 0,8,...,56

    __shared__ float sAT[Vv * Vv];     // 16 KB, [w][v]
    __shared__ float sX[8][Vv];        // 2 KB
    __shared__ float sH[8][Vv];        // 2 KB

    const int tid = threadIdx.x;

    // Per-thread W quad, leaky pre-selected: leaky(h*w) = h * (h>=0 ? wp : wn)
    float4 w4 = reinterpret_cast<const float4*>(W)[tid & 15];
    float4 wp, wn;
    wp.x = (w4.x >= 0.f) ? w4.x : NEG_SLOPE * w4.x;
    wp.y = (w4.y >= 0.f) ? w4.y : NEG_SLOPE * w4.y;
    wp.z = (w4.z >= 0.f) ? w4.z : NEG_SLOPE * w4.z;
    wp.w = (w4.w >= 0.f) ? w4.w : NEG_SLOPE * w4.w;
    wn.x = (w4.x >= 0.f) ? NEG_SLOPE * w4.x : w4.x;
    wn.y = (w4.y >= 0.f) ? NEG_SLOPE * w4.y : w4.y;
    wn.z = (w4.z >= 0.f) ? NEG_SLOPE * w4.z : w4.z;
    wn.w = (w4.w >= 0.f) ? NEG_SLOPE * w4.w : w4.w;

    // Stage adjT[t] (16 KB; LDG.128 coalesced, L2-shared across the 8 b-groups of t)
    {
        const float4* src = reinterpret_cast<const float4*>(g_adjT) + (size_t)t * 1024;
        float4* dst = reinterpret_cast<float4*>(sAT);
#pragma unroll
        for (int k = 0; k < 4; k++) dst[tid + k * 256] = src[tid + k * 256];
    }
    // Load XT[t][b0..b0+7][0:64] — 512 contiguous floats, fully coalesced.
    if (tid < 128) {
        const float4* src = reinterpret_cast<const float4*>(g_XT + (size_t)t * (Bb * Vv) + (size_t)b0 * Vv);
        reinterpret_cast<float4*>(&sX[0][0])[tid] = src[tid];
    }
    __syncthreads();

    // Mini-GEMM: thread (v = tid&63, g = tid>>6) computes h[g][v], h[g+4][v].
    {
        const int v = tid & 63;
        const int g = tid >> 6;
        const float4* x0q = reinterpret_cast<const float4*>(&sX[g][0]);
        const float4* x1q = reinterpret_cast<const float4*>(&sX[g + 4][0]);
        float a0 = 0.f, a1 = 0.f;
#pragma unroll
        for (int wq = 0; wq < 16; wq++) {
            float4 x0 = x0q[wq];
            float4 x1 = x1q[wq];
            float s0 = sAT[(4 * wq + 0) * 64 + v];
            float s1 = sAT[(4 * wq + 1) * 64 + v];
            float s2 = sAT[(4 * wq + 2) * 64 + v];
            float s3 = sAT[(4 * wq + 3) * 64 + v];
            a0 = fmaf(s0, x0.x, fmaf(s1, x0.y, fmaf(s2, x0.z, fmaf(s3, x0.w, a0))));
            a1 = fmaf(s0, x1.x, fmaf(s1, x1.y, fmaf(s2, x1.z, fmaf(s3, x1.w, a1))));
        }
        sH[g][v] = a0;
        sH[g + 4][v] = a1;
    }
    __syncthreads();

    // Store phase: 8 x 16 KB tiles of leaky(h*W), coalesced float4 streaming stores.
    float4* obase = reinterpret_cast<float4*>(out);
#pragma unroll
    for (int bb = 0; bb < 8; bb++) {
        float4* o = obase + ((size_t)(b0 + bb) * Tt + t) * 1024;
        const float* hrow = sH[bb];
#pragma unroll
        for (int k = 0; k < 4; k++) {
            int q = tid + k * 256;            // q&15 == tid&15, q>>4 = v
            float h = hrow[q >> 4];
            bool pos = (h >= 0.f);
            float4 r;
            r.x = h * (pos ? wp.x : wn.x);
            r.y = h * (pos ? wp.y : wn.y);
            r.z = h * (pos ? wp.z : wn.z);
            r.w = h * (pos ? wp.w : wn.w);
            __stcs(o + q, r);
        }
    }
}

extern "C" void kernel_launch(void* const* d_in, const int* in_sizes, int n_in,
                              void* d_out, int out_size) {
    const float* X = (const float*)d_in[0];   // [B, V, T]
    const float* A = (const float*)d_in[1];   // [T, V, V]
    const float* W = (const float*)d_in[2];   // [F, 1]
    float* out = (float*)d_out;               // [B, T, V*F]

    prep_combined<<<1536, 256>>>(A, X);
    dim3 grid(Tt, Bb / 8);
    fused_kernel<<<grid, 256>>>(W, out);
}